// round 6
// baseline (speedup 1.0000x reference)
#include <cuda_runtime.h>
#include <cstdint>

#define TOKENS 64
#define IN_F   4096
#define OUT_F  11008
#define RANK   16
#define BN     80
#define BK     32
#define NITER  (IN_F / BK)   // 128
#define NCTA   138           // ceil(11008/80)
#define NTHR   640           // 20 warps: 4m x 5n

// scratch
__device__ float g_tp[4 * TOKENS * RANK];               // k-quarter partials of t
__device__ float g_xfrag[NITER * 16 * 32 * 4];          // 1 MB, tf32-hi x fragments

// ---------------------------------------------------------------------------
__device__ __forceinline__ uint32_t smem_u32(const void* p) {
    uint32_t a;
    asm("{ .reg .u64 t; cvta.to.shared.u64 t, %1; cvt.u32.u64 %0, t; }" : "=r"(a) : "l"(p));
    return a;
}
__device__ __forceinline__ void cp16(void* dst_smem, const void* src) {
    asm volatile("cp.async.cg.shared.global [%0], [%1], 16;"
                 :: "r"(smem_u32(dst_smem)), "l"(src));
}
__device__ __forceinline__ void mma_tf32(float* d, const uint32_t* a, const uint32_t* b) {
    asm volatile("mma.sync.aligned.m16n8k8.row.col.f32.tf32.tf32.f32 "
        "{%0,%1,%2,%3}, {%4,%5,%6,%7}, {%8,%9}, {%0,%1,%2,%3};"
        : "+f"(d[0]), "+f"(d[1]), "+f"(d[2]), "+f"(d[3])
        : "r"(a[0]), "r"(a[1]), "r"(a[2]), "r"(a[3]), "r"(b[0]), "r"(b[1]));
}
__device__ __forceinline__ float tf32_rn(float v) {
    uint32_t h;
    asm("cvt.rna.tf32.f32 %0, %1;" : "=r"(h) : "f"(v));
    return __uint_as_float(h);
}

// ---------------------------------------------------------------------------
// Prep kernel (512 blocks x 256 threads):
//   blocks [0,256):  pack x into tf32-hi m16n8k8 A-fragments
//   blocks [256,512): t partials over K-quarters
// ---------------------------------------------------------------------------
__global__ void __launch_bounds__(256) prep_kernel(
    const float* __restrict__ x, const float* __restrict__ A)
{
    if (blockIdx.x < 256) {
        const int gid  = blockIdx.x * 256 + threadIdx.x;   // 65536
        const int lane = gid & 31;
        const int ks   = (gid >> 5) & 3;
        const int mt   = (gid >> 7) & 3;
        const int i    = gid >> 9;
        const int m    = mt * 16 + (lane >> 2);
        const int k    = i * BK + ks * 8 + (lane & 3);

        const float h00 = tf32_rn(x[m * IN_F + k]);
        const float h01 = tf32_rn(x[m * IN_F + k + 4]);
        const float h10 = tf32_rn(x[(m + 8) * IN_F + k]);
        const float h11 = tf32_rn(x[(m + 8) * IN_F + k + 4]);

        const int slot = mt * 4 + ks;
        *(float4*)(g_xfrag + ((size_t)i * 16 + slot) * 128 + lane * 4) =
            make_float4(h00, h10, h01, h11);
    } else {
        const int b   = blockIdx.x - 256;
        const int m   = b >> 2, q = b & 3;
        const int tid = threadIdx.x;
        const int wid = tid >> 5, lane = tid & 31;
        const int k4  = q * 256 + tid;
        const float4 xv = ((const float4*)(x + (size_t)m * IN_F))[k4];
        const float4* A4 = (const float4*)A;

        float racc[RANK];
#pragma unroll
        for (int r = 0; r < RANK; r++) {
            const float4 av = A4[r * 1024 + k4];
            racc[r] = xv.x * av.x + xv.y * av.y + xv.z * av.z + xv.w * av.w;
        }
#pragma unroll
        for (int r = 0; r < RANK; r++)
#pragma unroll
            for (int o = 16; o; o >>= 1)
                racc[r] += __shfl_xor_sync(0xFFFFFFFFu, racc[r], o);

        __shared__ float sp[8][RANK];
        if (lane == 0)
#pragma unroll
            for (int r = 0; r < RANK; r++) sp[wid][r] = racc[r];
        __syncthreads();
        if (tid < RANK) {
            float s = 0.0f;
#pragma unroll
            for (int w = 0; w < 8; w++) s += sp[w][tid];
            g_tp[(q * TOKENS + m) * RANK + tid] = s;
        }
    }
}

// ---------------------------------------------------------------------------
// GEMM: single-pass tf32, W fed raw (HW truncation, bias-corrected via scale).
// CTA: 64 tok x 80 ch. 20 warps (4m x 5n), warp tile 16 tok x 16 ch.
// 6-stage cp.async pipeline, one __syncthreads per iteration.
// ---------------------------------------------------------------------------
#define XS_SZ    8192                  // 16 slots * 128 floats
#define WS_SZ    11520                 // 80 rows * 36 floats * 4B
#define STAGE_SZ (XS_SZ + WS_SZ)       // 19712
#define NSTAGE   6
#define OFF_T    (NSTAGE * STAGE_SZ)   // 118272
#define SMEM_SZ  (OFF_T + TOKENS * RANK * 4)   // 122368

__global__ void __launch_bounds__(NTHR, 1) qgemm_tf32(
    const float* __restrict__ W,     const float* __restrict__ scale,
    const float* __restrict__ Bl,    const float* __restrict__ bias,
    float* __restrict__ out)
{
    extern __shared__ char smem[];
    float* sT = (float*)(smem + OFF_T);
    const int tid  = threadIdx.x;
    const int n0   = blockIdx.x * BN;
    const int warp = tid >> 5, lane = tid & 31;
    const int wm = warp & 3, wn = warp >> 2;   // 4m x 5n warp grid
    const int g  = lane >> 2, j = lane & 3;

    float acc[2][4];
#pragma unroll
    for (int b = 0; b < 2; b++)
#pragma unroll
        for (int c = 0; c < 4; c++) acc[b][c] = 0.0f;

    // W loader mapping: 80 rows x 8 quads = 640 threads, 1 cp each (clamped)
    const int wr = tid >> 3, wq = tid & 7;
    int wrow = n0 + wr;
    if (wrow > OUT_F - 1) wrow = OUT_F - 1;
    const float* wsrc = W + (size_t)wrow * IN_F + wq * 4;

#define ISSUE_STAGE(s) do {                                                     \
    if ((s) < NITER) {                                                          \
        char* buf = smem + ((s) % NSTAGE) * STAGE_SZ;                           \
        if (tid < 512)                                                          \
            cp16(buf + tid * 16, g_xfrag + (size_t)(s) * 2048 + tid * 4);       \
        cp16(buf + XS_SZ + wr * 144 + wq * 16, wsrc + (size_t)(s) * BK);        \
    }                                                                           \
    asm volatile("cp.async.commit_group;" ::: "memory");                        \
} while (0)

    ISSUE_STAGE(0);
    ISSUE_STAGE(1);
    ISSUE_STAGE(2);
    ISSUE_STAGE(3);
    ISSUE_STAGE(4);

    // reduce t partials into smem (overlaps with in-flight stages)
    for (int e = tid; e < TOKENS * RANK; e += NTHR)
        sT[e] = g_tp[e] + g_tp[1024 + e] + g_tp[2048 + e] + g_tp[3072 + e];

#pragma unroll 1
    for (int i = 0; i < NITER; i++) {
        asm volatile("cp.async.wait_group 4;" ::: "memory");
        __syncthreads();
        const char* buf = smem + (i % NSTAGE) * STAGE_SZ;
        const uint32_t* xs = (const uint32_t*)buf;
        const uint32_t* ws = (const uint32_t*)(buf + XS_SZ);

#pragma unroll
        for (int ks = 0; ks < 4; ks++) {
            uint32_t a[4];
            const uint4 v = *(const uint4*)(xs + (wm * 4 + ks) * 128 + lane * 4);
            a[0] = v.x; a[1] = v.y; a[2] = v.z; a[3] = v.w;
            uint32_t b[2][2];
#pragma unroll
            for (int nt = 0; nt < 2; nt++) {
                const int n = wn * 16 + nt * 8 + g;
                b[nt][0] = ws[n * 36 + ks * 8 + j];
                b[nt][1] = ws[n * 36 + ks * 8 + j + 4];
            }
            mma_tf32(acc[0], a, b[0]);
            mma_tf32(acc[1], a, b[1]);
        }
        // stage i+5 writes buffer (i+5)%6 — not read until iter i+5; safe
        ISSUE_STAGE(i + 5);
    }

    // epilogue: tf32-truncation bias correction folded into scale
    const float corr = 1.00048828125f;   // 1 + 2^-11
    const int tokA = wm * 16 + g;
    const int tokB = tokA + 8;
    float4 tA0 = *(const float4*)(sT + tokA * RANK);
    float4 tA1 = *(const float4*)(sT + tokA * RANK + 4);
    float4 tA2 = *(const float4*)(sT + tokA * RANK + 8);
    float4 tA3 = *(const float4*)(sT + tokA * RANK + 12);
    float4 tB0 = *(const float4*)(sT + tokB * RANK);
    float4 tB1 = *(const float4*)(sT + tokB * RANK + 4);
    float4 tB2 = *(const float4*)(sT + tokB * RANK + 8);
    float4 tB3 = *(const float4*)(sT + tokB * RANK + 12);
#pragma unroll
    for (int nt = 0; nt < 2; nt++) {
        const int ch = n0 + wn * 16 + nt * 8 + 2 * j;
        if (ch >= OUT_F) continue;
        const float2 sc = *(const float2*)(scale + ch);
        const float2 bi = *(const float2*)(bias + ch);
        const float* bl0 = Bl + (size_t)ch * RANK;
        const float* bl1 = bl0 + RANK;
        float l0 = 0.f, l0b = 0.f, l1 = 0.f, l1b = 0.f;
#pragma unroll
        for (int q = 0; q < 4; q++) {
            const float4 b0 = ((const float4*)bl0)[q];
            const float4 b1 = ((const float4*)bl1)[q];
            const float4 ta = (q == 0) ? tA0 : (q == 1) ? tA1 : (q == 2) ? tA2 : tA3;
            const float4 tb = (q == 0) ? tB0 : (q == 1) ? tB1 : (q == 2) ? tB2 : tB3;
            l0  += ta.x * b0.x + ta.y * b0.y + ta.z * b0.z + ta.w * b0.w;
            l1  += ta.x * b1.x + ta.y * b1.y + ta.z * b1.z + ta.w * b1.w;
            l0b += tb.x * b0.x + tb.y * b0.y + tb.z * b0.z + tb.w * b0.w;
            l1b += tb.x * b1.x + tb.y * b1.y + tb.z * b1.z + tb.w * b1.w;
        }
        const float s0 = sc.x * corr, s1 = sc.y * corr;
        float2 oA = make_float2(acc[nt][0] * s0 + l0  + bi.x,
                                acc[nt][1] * s1 + l1  + bi.y);
        float2 oB = make_float2(acc[nt][2] * s0 + l0b + bi.x,
                                acc[nt][3] * s1 + l1b + bi.y);
        *(float2*)(out + (size_t)tokA * OUT_F + ch) = oA;
        *(float2*)(out + (size_t)tokB * OUT_F + ch) = oB;
    }
}

// ---------------------------------------------------------------------------
extern "C" void kernel_launch(void* const* d_in, const int* in_sizes, int n_in,
                              void* d_out, int out_size)
{
    const float* x     = (const float*)d_in[0];
    const float* W     = (const float*)d_in[1];
    const float* scale = (const float*)d_in[2];
    const float* A     = (const float*)d_in[3];
    const float* B     = (const float*)d_in[4];
    const float* bias  = (const float*)d_in[5];
    float* out = (float*)d_out;

    cudaFuncSetAttribute(qgemm_tf32, cudaFuncAttributeMaxDynamicSharedMemorySize, SMEM_SZ);
    prep_kernel<<<512, 256>>>(x, A);
    qgemm_tf32<<<NCTA, NTHR, SMEM_SZ>>>(W, scale, B, bias, out);
}

// round 7
// speedup vs baseline: 1.2879x; 1.2879x over previous
#include <cuda_runtime.h>
#include <cstdint>

#define TOKENS 64
#define IN_F   4096
#define OUT_F  11008
#define RANK   16
#define BN     96
#define BK     32
#define NITER  (IN_F / BK)   // 128
#define NCTA   115           // ceil(11008/96)
#define NTHR   384           // 12 warps = 3 wn x 4 kg

// scratch
__device__ float g_tp[4 * TOKENS * RANK];               // k-quarter partials of t
__device__ float g_xfrag[NITER * 16 * 32 * 4];          // 1 MB, tf32-hi x fragments

// ---------------------------------------------------------------------------
__device__ __forceinline__ uint32_t smem_u32(const void* p) {
    uint32_t a;
    asm("{ .reg .u64 t; cvta.to.shared.u64 t, %1; cvt.u32.u64 %0, t; }" : "=r"(a) : "l"(p));
    return a;
}
__device__ __forceinline__ void cp16(void* dst_smem, const void* src) {
    asm volatile("cp.async.cg.shared.global [%0], [%1], 16;"
                 :: "r"(smem_u32(dst_smem)), "l"(src));
}
__device__ __forceinline__ void mma_tf32(float* d, const uint32_t* a, const uint32_t* b) {
    asm volatile("mma.sync.aligned.m16n8k8.row.col.f32.tf32.tf32.f32 "
        "{%0,%1,%2,%3}, {%4,%5,%6,%7}, {%8,%9}, {%0,%1,%2,%3};"
        : "+f"(d[0]), "+f"(d[1]), "+f"(d[2]), "+f"(d[3])
        : "r"(a[0]), "r"(a[1]), "r"(a[2]), "r"(a[3]), "r"(b[0]), "r"(b[1]));
}
__device__ __forceinline__ float tf32_rn(float v) {
    uint32_t h;
    asm("cvt.rna.tf32.f32 %0, %1;" : "=r"(h) : "f"(v));
    return __uint_as_float(h);
}

// ---------------------------------------------------------------------------
// Prep kernel (512 blocks x 256 threads):
//   blocks [0,256):  pack x into tf32-hi m16n8k8 A-fragments
//   blocks [256,512): t partials over K-quarters
// ---------------------------------------------------------------------------
__global__ void __launch_bounds__(256) prep_kernel(
    const float* __restrict__ x, const float* __restrict__ A)
{
    if (blockIdx.x < 256) {
        const int gid  = blockIdx.x * 256 + threadIdx.x;   // 65536
        const int lane = gid & 31;
        const int ks   = (gid >> 5) & 3;
        const int mt   = (gid >> 7) & 3;
        const int i    = gid >> 9;
        const int m    = mt * 16 + (lane >> 2);
        const int k    = i * BK + ks * 8 + (lane & 3);

        const float h00 = tf32_rn(x[m * IN_F + k]);
        const float h01 = tf32_rn(x[m * IN_F + k + 4]);
        const float h10 = tf32_rn(x[(m + 8) * IN_F + k]);
        const float h11 = tf32_rn(x[(m + 8) * IN_F + k + 4]);

        const int slot = mt * 4 + ks;
        *(float4*)(g_xfrag + ((size_t)i * 16 + slot) * 128 + lane * 4) =
            make_float4(h00, h10, h01, h11);
    } else {
        const int b   = blockIdx.x - 256;
        const int m   = b >> 2, q = b & 3;
        const int tid = threadIdx.x;
        const int wid = tid >> 5, lane = tid & 31;
        const int k4  = q * 256 + tid;
        const float4 xv = ((const float4*)(x + (size_t)m * IN_F))[k4];
        const float4* A4 = (const float4*)A;

        float racc[RANK];
#pragma unroll
        for (int r = 0; r < RANK; r++) {
            const float4 av = A4[r * 1024 + k4];
            racc[r] = xv.x * av.x + xv.y * av.y + xv.z * av.z + xv.w * av.w;
        }
#pragma unroll
        for (int r = 0; r < RANK; r++)
#pragma unroll
            for (int o = 16; o; o >>= 1)
                racc[r] += __shfl_xor_sync(0xFFFFFFFFu, racc[r], o);

        __shared__ float sp[8][RANK];
        if (lane == 0)
#pragma unroll
            for (int r = 0; r < RANK; r++) sp[wid][r] = racc[r];
        __syncthreads();
        if (tid < RANK) {
            float s = 0.0f;
#pragma unroll
            for (int w = 0; w < 8; w++) s += sp[w][tid];
            g_tp[(q * TOKENS + m) * RANK + tid] = s;
        }
    }
}

// ---------------------------------------------------------------------------
// GEMM: single-pass tf32, W fed raw (HW truncation, bias-corrected via scale).
// CTA: 64 tok x 96 ch. 12 warps = 3 wn x 4 kg, warp tile 64 tok x 32 ch,
// each warp owns one k8 slice per BK=32 iteration (4-way K split).
// 8-stage cp.async pipeline, one __syncthreads per iteration.
// ---------------------------------------------------------------------------
#define XS_SZ    8192                  // 16 slots * 128 floats
#define WS_SZ    13824                 // 96 rows * 36 floats * 4B
#define STAGE_SZ (XS_SZ + WS_SZ)       // 22016
#define NSTAGE   8
#define OFF_T    (NSTAGE * STAGE_SZ)   // 176128
#define SMEM_SZ  (OFF_T + TOKENS * RANK * 4)   // 180224

__global__ void __launch_bounds__(NTHR, 1) qgemm_tf32(
    const float* __restrict__ W,     const float* __restrict__ scale,
    const float* __restrict__ Bl,    const float* __restrict__ bias,
    float* __restrict__ out)
{
    extern __shared__ char smem[];
    float* sT = (float*)(smem + OFF_T);
    const int tid  = threadIdx.x;
    const int n0   = blockIdx.x * BN;
    const int warp = tid >> 5, lane = tid & 31;
    const int wn = warp % 3, kg = warp / 3;    // 3 n-warps x 4 k-groups
    const int g  = lane >> 2, j = lane & 3;

    float4 acc[4][4];                          // [mt][nt], 16-B aligned
#pragma unroll
    for (int a = 0; a < 4; a++)
#pragma unroll
        for (int b = 0; b < 4; b++) acc[a][b] = make_float4(0.f, 0.f, 0.f, 0.f);

    // W loader mapping: 96 rows x 8 quads = 768 chunks, 2 per thread (clamped)
    const int wr0 = tid >> 3,           wq0 = tid & 7;
    const int wr1 = (tid + 384) >> 3,   wq1 = (tid + 384) & 7;
    int row0 = n0 + wr0; if (row0 > OUT_F - 1) row0 = OUT_F - 1;
    int row1 = n0 + wr1; if (row1 > OUT_F - 1) row1 = OUT_F - 1;
    const float* wsrc0 = W + (size_t)row0 * IN_F + wq0 * 4;
    const float* wsrc1 = W + (size_t)row1 * IN_F + wq1 * 4;

#define ISSUE_STAGE(s) do {                                                     \
    if ((s) < NITER) {                                                          \
        char* buf = smem + ((s) & 7) * STAGE_SZ;                                \
        cp16(buf + tid * 16, g_xfrag + (size_t)(s) * 2048 + tid * 4);           \
        if (tid < 128)                                                          \
            cp16(buf + (tid + 384) * 16,                                        \
                 g_xfrag + (size_t)(s) * 2048 + (tid + 384) * 4);               \
        cp16(buf + XS_SZ + wr0 * 144 + wq0 * 16, wsrc0 + (size_t)(s) * BK);     \
        cp16(buf + XS_SZ + wr1 * 144 + wq1 * 16, wsrc1 + (size_t)(s) * BK);     \
    }                                                                           \
    asm volatile("cp.async.commit_group;" ::: "memory");                        \
} while (0)

    ISSUE_STAGE(0); ISSUE_STAGE(1); ISSUE_STAGE(2); ISSUE_STAGE(3);
    ISSUE_STAGE(4); ISSUE_STAGE(5); ISSUE_STAGE(6);

    // reduce t partials into smem (overlaps with in-flight stages)
    for (int e = tid; e < TOKENS * RANK; e += NTHR)
        sT[e] = g_tp[e] + g_tp[1024 + e] + g_tp[2048 + e] + g_tp[3072 + e];

#pragma unroll 1
    for (int i = 0; i < NITER; i++) {
        asm volatile("cp.async.wait_group 5;" ::: "memory");
        __syncthreads();
        const char* buf = smem + (i & 7) * STAGE_SZ;
        const uint32_t* xs = (const uint32_t*)buf;
        const uint32_t* ws = (const uint32_t*)(buf + XS_SZ);

        uint32_t a[4][4];
#pragma unroll
        for (int mt = 0; mt < 4; mt++) {
            const uint4 v = *(const uint4*)(xs + (mt * 4 + kg) * 128 + lane * 4);
            a[mt][0] = v.x; a[mt][1] = v.y; a[mt][2] = v.z; a[mt][3] = v.w;
        }
        uint32_t b[4][2];
#pragma unroll
        for (int nt = 0; nt < 4; nt++) {
            const int n = wn * 32 + nt * 8 + g;
            b[nt][0] = ws[n * 36 + kg * 8 + j];
            b[nt][1] = ws[n * 36 + kg * 8 + j + 4];
        }
#pragma unroll
        for (int mt = 0; mt < 4; mt++)
#pragma unroll
            for (int nt = 0; nt < 4; nt++)
                mma_tf32((float*)&acc[mt][nt], a[mt], b[nt]);

        // stage i+7 writes buffer (i+7)&7 != i&7; all warps past barrier i: safe
        ISSUE_STAGE(i + 7);
    }
    __syncthreads();   // all reads of stage buffers done; reuse as reduce area

    // ---- 4-way K reduction through smem: slot layout conflict-free -------
    float* red = (float*)smem;
#pragma unroll
    for (int nt = 0; nt < 4; nt++)
#pragma unroll
        for (int mt = 0; mt < 4; mt++) {
            const int slot = ((nt * 4 + kg) * 3 + wn) * 4 + mt;
            *(float4*)(red + slot * 128 + lane * 4) = acc[mt][nt];
        }
    __syncthreads();

    float4 f[4];
#pragma unroll
    for (int mt = 0; mt < 4; mt++) f[mt] = make_float4(0.f, 0.f, 0.f, 0.f);
#pragma unroll
    for (int src = 0; src < 4; src++)
#pragma unroll
        for (int mt = 0; mt < 4; mt++) {
            const int slot = ((kg * 4 + src) * 3 + wn) * 4 + mt;
            const float4 v = *(const float4*)(red + slot * 128 + lane * 4);
            f[mt].x += v.x; f[mt].y += v.y; f[mt].z += v.z; f[mt].w += v.w;
        }

    // ---- epilogue: warp (wn,kg) owns nt = kg ------------------------------
    const float corr = 1.00048828125f;   // 1 + 2^-11 tf32-truncation bias fix
    const int ch = n0 + wn * 32 + kg * 8 + 2 * j;
    if (ch < OUT_F) {
        const float2 sc = *(const float2*)(scale + ch);
        const float2 bi = *(const float2*)(bias + ch);
        const float s0 = sc.x * corr, s1 = sc.y * corr;
        const float4* bl0 = (const float4*)(Bl + (size_t)ch * RANK);
        const float4* bl1 = (const float4*)(Bl + (size_t)(ch + 1) * RANK);
        float4 b0[4], b1[4];
#pragma unroll
        for (int q = 0; q < 4; q++) { b0[q] = bl0[q]; b1[q] = bl1[q]; }

#pragma unroll
        for (int mt = 0; mt < 4; mt++) {
            const int tokA = mt * 16 + g;
            const int tokB = tokA + 8;
            float l0 = 0.f, l1 = 0.f, l0b = 0.f, l1b = 0.f;
#pragma unroll
            for (int q = 0; q < 4; q++) {
                const float4 ta = ((const float4*)(sT + tokA * RANK))[q];
                const float4 tb = ((const float4*)(sT + tokB * RANK))[q];
                l0  += ta.x * b0[q].x + ta.y * b0[q].y + ta.z * b0[q].z + ta.w * b0[q].w;
                l1  += ta.x * b1[q].x + ta.y * b1[q].y + ta.z * b1[q].z + ta.w * b1[q].w;
                l0b += tb.x * b0[q].x + tb.y * b0[q].y + tb.z * b0[q].z + tb.w * b0[q].w;
                l1b += tb.x * b1[q].x + tb.y * b1[q].y + tb.z * b1[q].z + tb.w * b1[q].w;
            }
            *(float2*)(out + (size_t)tokA * OUT_F + ch) =
                make_float2(f[mt].x * s0 + l0 + bi.x, f[mt].y * s1 + l1 + bi.y);
            *(float2*)(out + (size_t)tokB * OUT_F + ch) =
                make_float2(f[mt].z * s0 + l0b + bi.x, f[mt].w * s1 + l1b + bi.y);
        }
    }
}

// ---------------------------------------------------------------------------
extern "C" void kernel_launch(void* const* d_in, const int* in_sizes, int n_in,
                              void* d_out, int out_size)
{
    const float* x     = (const float*)d_in[0];
    const float* W     = (const float*)d_in[1];
    const float* scale = (const float*)d_in[2];
    const float* A     = (const float*)d_in[3];
    const float* B     = (const float*)d_in[4];
    const float* bias  = (const float*)d_in[5];
    float* out = (float*)d_out;

    cudaFuncSetAttribute(qgemm_tf32, cudaFuncAttributeMaxDynamicSharedMemorySize, SMEM_SZ);
    prep_kernel<<<512, 256>>>(x, A);
    qgemm_tf32<<<NCTA, NTHR, SMEM_SZ>>>(W, scale, B, bias, out);
}